// round 14
// baseline (speedup 1.0000x reference)
#include <cuda_runtime.h>
#include <cuda_fp16.h>
#include <cstdint>
#include <cstddef>

#define NUMNODES 32768
#define NCHAIN   1024

// -------- global scratch (no allocations allowed) --------
__device__ __half g_ymsg[(size_t)NUMNODES * 1024];   // 64 MB msg buffer (fp16)
__device__ float  g_yself[(size_t)NUMNODES * 128];   // 16 MB self buffer (fp32)
__device__ float  g_alpha[(size_t)NUMNODES * 16];
__device__ float  g_alpha5[(size_t)NUMNODES];
__device__ float  g_bufA[(size_t)NUMNODES * 128];
__device__ float  g_bufB[(size_t)NUMNODES * 128];
__device__ __half g_xq[(size_t)NUMNODES * 128];      // fp16 activations
#define WSLOT (1152 * 128)
__device__ __half g_w16[3 * WSLOT];                  // fp16 weights [n][k]
__device__ float g_bias[3 * 1152];

// ================= PTX helpers (baseline ISA only) =================
__device__ __forceinline__ uint32_t smem_u32(const void* p) {
    uint32_t a;
    asm("{ .reg .u64 t; cvta.to.shared.u64 t, %1; cvt.u32.u64 %0, t; }" : "=r"(a) : "l"(p));
    return a;
}
__device__ __forceinline__ void cp16(uint32_t dst, const void* src) {
    asm volatile("{ .reg .u64 g; cvta.to.global.u64 g, %1; cp.async.cg.shared.global [%0], [g], 16; }"
        :: "r"(dst), "l"(src) : "memory");
}
__device__ __forceinline__ void cp_commit() {
    asm volatile("cp.async.commit_group;" ::: "memory");
}
__device__ __forceinline__ void cp_wait0() {
    asm volatile("cp.async.wait_group 0;" ::: "memory");
}
__device__ __forceinline__ void ldm_x4(uint32_t* r, uint32_t addr) {
    asm volatile("ldmatrix.sync.aligned.m8n8.x4.shared.b16 {%0,%1,%2,%3}, [%4];"
        : "=r"(r[0]), "=r"(r[1]), "=r"(r[2]), "=r"(r[3]) : "r"(addr));
}
__device__ __forceinline__ void mma_f16(float* d, const uint32_t* a, const uint32_t* b) {
    asm volatile(
        "mma.sync.aligned.m16n8k16.row.col.f32.f16.f16.f32 "
        "{%0,%1,%2,%3}, {%4,%5,%6,%7}, {%8,%9}, {%0,%1,%2,%3};"
        : "+f"(d[0]), "+f"(d[1]), "+f"(d[2]), "+f"(d[3])
        : "r"(a[0]), "r"(a[1]), "r"(a[2]), "r"(a[3]), "r"(b[0]), "r"(b[1]));
}
__device__ __forceinline__ float leaky(float v) { return (v > 0.f) ? v : 0.01f * v; }

// ================= combined weight convert (all 3 MMA layers) =================
__global__ __launch_bounds__(256) void convert_w_all(
    const float* __restrict__ Wm2, const float* __restrict__ bm2,
    const float* __restrict__ Ws2, const float* __restrict__ bs2,
    const float* __restrict__ Wm3, const float* __restrict__ bm3,
    const float* __restrict__ Ws3, const float* __restrict__ bs3,
    const float* __restrict__ Wm4, const float* __restrict__ bm4,
    const float* __restrict__ Ws4, const float* __restrict__ bs4,
    __half* __restrict__ w16, float* __restrict__ bias)
{
    int idx = blockIdx.x * 256 + threadIdx.x;
    int layer, K, COUT;
    const float *Wm, *bm, *Ws, *bs;
    if (idx < 1152 * 128) {
        layer = 0; K = 128; COUT = 128; Wm = Wm2; bm = bm2; Ws = Ws2; bs = bs2;
    } else if (idx < 2 * 1152 * 128) {
        idx -= 1152 * 128;
        layer = 1; K = 128; COUT = 64; Wm = Wm3; bm = bm3; Ws = Ws3; bs = bs3;
    } else if (idx < 2 * 1152 * 128 + 1152 * 64) {
        idx -= 2 * 1152 * 128;
        layer = 2; K = 64; COUT = 64; Wm = Wm4; bm = bm4; Ws = Ws4; bs = bs4;
    } else return;

    const int n = idx / K, k = idx % K;
    float v;
    if (n < 1024)             v = Wm[(size_t)k * 1024 + n];
    else if (n < 1024 + COUT) v = Ws[(size_t)k * COUT + (n - 1024)];
    else                      v = 0.f;
    w16[(size_t)layer * WSLOT + idx] = __float2half(v);
    if (k == 0)
        bias[layer * 1152 + n] = (n < 1024) ? bm[n] : ((n < 1024 + COUT) ? bs[n - 1024] : 0.f);
}

// ================= layer 1: alpha =================
__global__ __launch_bounds__(256) void alpha1(
    const float* __restrict__ x, const float* __restrict__ Wm,
    const float* __restrict__ bm, const float* __restrict__ att)
{
    __shared__ float wm_s[1024], bm_s[1024], att_s[1024];
    const int tid = threadIdx.x;
    for (int i = tid; i < 1024; i += 256) {
        wm_s[i] = Wm[i]; bm_s[i] = bm[i]; att_s[i] = att[i];
    }
    __syncthreads();

    const int w = tid >> 5, l = tid & 31;
    const int g = blockIdx.x * 32 + l;
    const float xv = x[g];
    const int base = w * 128;
    float a = 0.f;
    #pragma unroll 8
    for (int c = 0; c < 128; c++) {
        const float t = leaky(fmaf(xv, wm_s[base + c], bm_s[base + c]));
        a = fmaf(t, att_s[base + c], a);
    }
    g_alpha[(size_t)g * 8 + w] = a;
}

// ================= layer 1: output (agg + self + ELU -> fp16) =================
__global__ __launch_bounds__(256) void out1(
    const float* __restrict__ x,  const float* __restrict__ Wm,
    const float* __restrict__ bm, const float* __restrict__ Ws,
    const float* __restrict__ bs,
    __half* __restrict__ xq)
{
    constexpr int NPB = 32;
    __shared__ float wm_s[1024], bm_s[1024];
    __shared__ float ws_s[128], bs_s[128];
    __shared__ float wgt[NPB][16];
    __shared__ float xs[NPB + 2];

    const int tid = threadIdx.x;
    const int gBase = blockIdx.x * NPB;

    for (int i = tid; i < 1024; i += 256) { wm_s[i] = Wm[i]; bm_s[i] = bm[i]; }
    if (tid < 128) { ws_s[tid] = Ws[tid]; bs_s[tid] = bs[tid]; }
    if (tid < NPB + 2) {
        int gi = gBase + tid - 1;
        gi = (gi < 0) ? 0 : ((gi > NUMNODES - 1) ? NUMNODES - 1 : gi);
        xs[tid] = x[gi];
    }
    {
        const int node = tid >> 3, h = tid & 7;
        const int g = gBase + node;
        const int nch = g & (NCHAIN - 1);
        float el, er;
        if (nch == 0)               { el = 0.f; er = 1.f; }
        else if (nch == NCHAIN - 1) { el = 1.f; er = 0.f; }
        else {
            const float al = g_alpha[(size_t)(g - 1) * 8 + h];
            const float ar = g_alpha[(size_t)(g + 1) * 8 + h];
            const float mx = fmaxf(al, ar);
            el = expf(al - mx); er = expf(ar - mx);
        }
        const float inv = (1.f / ((el + er) + 1e-16f)) * 0.125f;
        wgt[node][h]     = el * inv;
        wgt[node][8 + h] = er * inv;
    }
    __syncthreads();

    const int col = tid & 127;
    float wmv[8], bmv[8];
    #pragma unroll
    for (int h = 0; h < 8; h++) { wmv[h] = wm_s[h * 128 + col]; bmv[h] = bm_s[h * 128 + col]; }
    const float wsc = ws_s[col], bsc = bs_s[col];

    for (int n = (tid >> 7); n < NPB; n += 2) {
        const int g = gBase + n;
        const float xL = xs[n], xS = xs[n + 1], xR = xs[n + 2];
        float s = fmaf(xS, wsc, bsc);
        #pragma unroll
        for (int h = 0; h < 8; h++) {
            const float tL = leaky(fmaf(xL, wmv[h], bmv[h]));
            const float tR = leaky(fmaf(xR, wmv[h], bmv[h]));
            s = fmaf(wgt[n][h], tL, s);
            s = fmaf(wgt[n][8 + h], tR, s);
        }
        s = (s > 0.f) ? s : expm1f(s);           // ELU
        xq[(size_t)g * 128 + col] = __float2half(s);
    }
}

// ================= mma.sync fused GEMM (layers 2-4) =================
// grid (512, 5): ny<4 -> pair of msg 128-col tiles (A loaded once);
// ny==4 -> self tile. 8 warps (2M x 4N), warp tile 32m x 32n.
template<int K, int C>
__global__ __launch_bounds__(256, 3) void gemm_mma(
    const __half* __restrict__ xq, const __half* __restrict__ w16,
    const float* __restrict__ bias, const float* __restrict__ att,
    __half* __restrict__ ymsg, float* __restrict__ yself)
{
    constexpr int SROW = K + 8;
    constexpr int STRIDE = 136;                           // staging row stride (halfs)
    extern __shared__ __align__(16) char smem[];
    __half* sA = reinterpret_cast<__half*>(smem);
    __half* sB = sA + 64 * SROW;
    __half* sStage = sB + 128 * SROW;                     // dedicated staging
    float* alpha_s = reinterpret_cast<float*>(sStage + 64 * STRIDE);   // [4][64]

    const int tid  = threadIdx.x;
    const int lane = tid & 31;
    const int wid  = tid >> 5;
    const int warpM = wid >> 2;          // 0..1
    const int warpN = wid & 3;           // 0..3
    const int g = lane >> 2, t = lane & 3;

    const int mBase = blockIdx.x * 64;
    const int ny = blockIdx.y;
    const bool isMsg = (ny < 4);
    const int nBase0 = isMsg ? ny * 256 : 1024;

    constexpr int VPR = K / 8;
    const uint32_t uA = smem_u32(sA);
    const uint32_t uB = smem_u32(sB);

    // ---- initial cp.async loads: A tile + first B tile ----
    {
        const uint4* gA = reinterpret_cast<const uint4*>(xq + (size_t)mBase * K);
        const uint4* gB = reinterpret_cast<const uint4*>(w16 + (size_t)nBase0 * K);
        #pragma unroll
        for (int i = 0; i < (64 * VPR) / 256; i++) {
            const int idx = tid + i * 256;
            const int row = idx / VPR, kv = idx % VPR;
            const uint32_t so = (row * (SROW / 8) + kv) * 16;
            cp16(uA + so, gA + idx);
        }
        #pragma unroll
        for (int i = 0; i < (128 * VPR) / 256; i++) {
            const int idx = tid + i * 256;
            const int row = idx / VPR, kv = idx % VPR;
            const uint32_t so = (row * (SROW / 8) + kv) * 16;
            cp16(uB + so, gB + idx);
        }
        cp_commit();
        cp_wait0();
    }
    __syncthreads();

    const uint32_t aOfs = ((warpM * 32 + (lane & 15)) * SROW + ((lane >> 4) << 3)) * 2;
    const uint32_t bOfs = ((warpN * 32 + ((lane >> 4) << 3) + (lane & 7)) * SROW
                          + (((lane >> 3) & 1) << 3)) * 2;

    const int NPASS = isMsg ? 2 : 1;
    for (int p = 0; p < NPASS; p++) {
        const int nBase = nBase0 + p * 128;

        // ---- MMA mainloop ----
        float acc[2][4][4];
        #pragma unroll
        for (int mi = 0; mi < 2; mi++)
            #pragma unroll
            for (int ni = 0; ni < 4; ni++)
                #pragma unroll
                for (int e = 0; e < 4; e++) acc[mi][ni][e] = 0.f;

        #pragma unroll
        for (int kc = 0; kc < K / 16; kc++) {
            const uint32_t kByte = kc * 32;
            uint32_t a0[4], a1[4], r0[4], r1[4];
            ldm_x4(a0, uA + aOfs + kByte);
            ldm_x4(a1, uA + aOfs + (16 * SROW * 2) + kByte);
            ldm_x4(r0, uB + bOfs + kByte);
            ldm_x4(r1, uB + bOfs + (16 * SROW * 2) + kByte);
            mma_f16(acc[0][0], a0, r0);     mma_f16(acc[1][0], a1, r0);
            mma_f16(acc[0][1], a0, r0 + 2); mma_f16(acc[1][1], a1, r0 + 2);
            mma_f16(acc[0][2], a0, r1);     mma_f16(acc[1][2], a1, r1);
            mma_f16(acc[0][3], a0, r1 + 2); mma_f16(acc[1][3], a1, r1 + 2);
        }

        __syncthreads();   // all B-tile reads complete

        if (isMsg) {
            // overlap: kick off B-tile for pass 1 while epilogue runs
            if (p == 0) {
                const uint4* gB = reinterpret_cast<const uint4*>(w16 + (size_t)(nBase0 + 128) * K);
                #pragma unroll
                for (int i = 0; i < (128 * VPR) / 256; i++) {
                    const int idx = tid + i * 256;
                    const int row = idx / VPR, kv = idx % VPR;
                    const uint32_t so = (row * (SROW / 8) + kv) * 16;
                    cp16(uB + so, gB + idx);
                }
                cp_commit();
            }

            // ---- epilogue ----
            float alphaLoc[2][2] = {{0.f, 0.f}, {0.f, 0.f}};
            #pragma unroll
            for (int ni = 0; ni < 4; ni++) {
                const int n0l = warpN * 32 + ni * 8 + 2 * t;
                const int n0 = nBase + n0l;
                const float2 bb = *reinterpret_cast<const float2*>(&bias[n0]);
                const float2 aa = *reinterpret_cast<const float2*>(&att[n0]);
                #pragma unroll
                for (int mi = 0; mi < 2; mi++) {
                    float v0 = leaky(acc[mi][ni][0] + bb.x);
                    float v1 = leaky(acc[mi][ni][1] + bb.y);
                    float v2 = leaky(acc[mi][ni][2] + bb.x);
                    float v3 = leaky(acc[mi][ni][3] + bb.y);
                    alphaLoc[mi][0] = fmaf(v0, aa.x, fmaf(v1, aa.y, alphaLoc[mi][0]));
                    alphaLoc[mi][1] = fmaf(v2, aa.x, fmaf(v3, aa.y, alphaLoc[mi][1]));
                    const int r0l = warpM * 32 + mi * 16 + g;
                    *reinterpret_cast<__half2*>(sStage + r0l * STRIDE + n0l) =
                        __floats2half2_rn(v0, v1);
                    *reinterpret_cast<__half2*>(sStage + (r0l + 8) * STRIDE + n0l) =
                        __floats2half2_rn(v2, v3);
                }
            }

            #pragma unroll
            for (int mi = 0; mi < 2; mi++)
                #pragma unroll
                for (int rh = 0; rh < 2; rh++) {
                    float s = alphaLoc[mi][rh];
                    s += __shfl_xor_sync(0xffffffffu, s, 1);
                    s += __shfl_xor_sync(0xffffffffu, s, 2);
                    alphaLoc[mi][rh] = s;
                }
            if (t == 0) {
                #pragma unroll
                for (int mi = 0; mi < 2; mi++) {
                    const int lr = warpM * 32 + mi * 16 + g;
                    alpha_s[warpN * 64 + lr]     = alphaLoc[mi][0];
                    alpha_s[warpN * 64 + lr + 8] = alphaLoc[mi][1];
                }
            }
            __syncthreads();   // stage + alpha_s writes visible

            const int tileIdx = ny * 2 + p;
            if (C == 128) {
                if (tid < 64) {
                    const float s = alpha_s[tid] + alpha_s[64 + tid] +
                                    alpha_s[128 + tid] + alpha_s[192 + tid];
                    g_alpha[(size_t)(mBase + tid) * 8 + tileIdx] = s;
                }
            } else {
                if (tid < 128) {
                    const int r = tid & 63, hh = tid >> 6;
                    const float s = alpha_s[hh * 128 + r] + alpha_s[hh * 128 + 64 + r];
                    g_alpha[(size_t)(mBase + r) * 16 + tileIdx * 2 + hh] = s;
                }
            }

            // coalesced staging -> global copy
            #pragma unroll
            for (int it = 0; it < 4; it++) {
                const int idx = tid + it * 256;
                const int r = idx >> 4;
                const int c8 = idx & 15;
                const uint4 v = *reinterpret_cast<const uint4*>(sStage + r * STRIDE + c8 * 8);
                *reinterpret_cast<uint4*>(ymsg + (size_t)(mBase + r) * 1024 + nBase + c8 * 8) = v;
            }

            if (p == 0) {
                cp_wait0();
                __syncthreads();
            }
        } else {
            // self tile: direct fp32 stores
            #pragma unroll
            for (int ni = 0; ni < 4; ni++) {
                const int n0 = nBase + warpN * 32 + ni * 8 + 2 * t;
                const float2 bb = *reinterpret_cast<const float2*>(&bias[n0]);
                const int c = n0 - 1024;
                #pragma unroll
                for (int mi = 0; mi < 2; mi++) {
                    const int row0 = mBase + warpM * 32 + mi * 16 + g;
                    *reinterpret_cast<float2*>(yself + (size_t)row0 * 128 + c) =
                        make_float2(acc[mi][ni][0] + bb.x, acc[mi][ni][1] + bb.y);
                    *reinterpret_cast<float2*>(yself + (size_t)(row0 + 8) * 128 + c) =
                        make_float2(acc[mi][ni][2] + bb.x, acc[mi][ni][3] + bb.y);
                }
            }
        }
    }
}

// ================= aggregation stencil (fp16 msg + fp32 self), 8 cols/thread =================
template<int C, int H>
__global__ __launch_bounds__(256) void agg2h(
    const __half* __restrict__ ymsg, const float* __restrict__ yself,
    __half* __restrict__ xq)
{
    constexpr int TPN = C / 8;
    constexpr int NPB = 256 / TPN;

    __shared__ float wl_s[NPB * H];
    __shared__ float wr_s[NPB * H];

    const int tid = threadIdx.x;
    const int gBase = blockIdx.x * NPB;

    for (int idx = tid; idx < NPB * H; idx += 256) {
        const int node = idx / H, h = idx % H;
        const int g = gBase + node;
        const int nch = g & (NCHAIN - 1);
        float el, er;
        if (nch == 0)               { el = 0.f; er = 1.f; }
        else if (nch == NCHAIN - 1) { el = 1.f; er = 0.f; }
        else {
            const float al = g_alpha[(size_t)(g - 1) * H + h];
            const float ar = g_alpha[(size_t)(g + 1) * H + h];
            const float mx = fmaxf(al, ar);
            el = expf(al - mx); er = expf(ar - mx);
        }
        const float inv = (1.f / ((el + er) + 1e-16f)) * (1.f / H);
        wl_s[idx] = el * inv;
        wr_s[idx] = er * inv;
    }
    __syncthreads();

    const int lane = tid % TPN, node = tid / TPN;
    const int g = gBase + node;
    const int nch = g & (NCHAIN - 1);
    const __half* rowL = ymsg + (size_t)((nch > 0)          ? g - 1 : g) * 1024;
    const __half* rowR = ymsg + (size_t)((nch < NCHAIN - 1) ? g + 1 : g) * 1024;
    const int c8 = lane * 8;

    float acc[8];
    #pragma unroll
    for (int e = 0; e < 8; e++) acc[e] = 0.f;

    #pragma unroll
    for (int h = 0; h < H; h++) {
        const float wl = wl_s[node * H + h];
        const float wr = wr_s[node * H + h];
        const uint4 uL = *reinterpret_cast<const uint4*>(rowL + h * C + c8);
        const uint4 uR = *reinterpret_cast<const uint4*>(rowR + h * C + c8);
        const uint32_t* pL = &uL.x;
        const uint32_t* pR = &uR.x;
        #pragma unroll
        for (int q = 0; q < 4; q++) {
            const float2 l = __half22float2(*reinterpret_cast<const __half2*>(&pL[q]));
            const float2 r = __half22float2(*reinterpret_cast<const __half2*>(&pR[q]));
            acc[2 * q]     = fmaf(wl, l.x, fmaf(wr, r.x, acc[2 * q]));
            acc[2 * q + 1] = fmaf(wl, l.y, fmaf(wr, r.y, acc[2 * q + 1]));
        }
    }
    const float4 s0 = *reinterpret_cast<const float4*>(yself + (size_t)g * 128 + c8);
    const float4 s1 = *reinterpret_cast<const float4*>(yself + (size_t)g * 128 + c8 + 4);
    acc[0] += s0.x; acc[1] += s0.y; acc[2] += s0.z; acc[3] += s0.w;
    acc[4] += s1.x; acc[5] += s1.y; acc[6] += s1.z; acc[7] += s1.w;

    __half hv[8];
    #pragma unroll
    for (int e = 0; e < 8; e++) {
        const float v = (acc[e] > 0.f) ? acc[e] : expm1f(acc[e]);  // ELU
        hv[e] = __float2half(v);
    }
    *reinterpret_cast<uint4*>(xq + (size_t)g * C + c8) = *reinterpret_cast<uint4*>(hv);
}

// ================= fused agg4 (C=64,H=16) + layer-5 msg/self =================
// NPB=32 nodes/block; phase A: agg -> x_s (fp32); phase B: msg5/self5 + alpha5.
__global__ __launch_bounds__(256) void agg4f(
    const __half* __restrict__ ymsg, const float* __restrict__ yself,
    const float* __restrict__ Wm5, const float* __restrict__ bm5,
    const float* __restrict__ Ws5, const float* __restrict__ bs5,
    const float* __restrict__ att5,
    float* __restrict__ y5)
{
    constexpr int C = 64, H = 16, TPN = 8, NPB = 32;

    __shared__ float wl_s[NPB * H];
    __shared__ float wr_s[NPB * H];
    __shared__ float x_s[NPB * 64];       // 8 KB
    __shared__ float w5_s[64 * 64];       // 16 KB: [k][j], j<32 msg, j>=32 self

    const int tid = threadIdx.x;
    const int gBase = blockIdx.x * NPB;

    for (int i = tid; i < 64 * 64; i += 256) {
        const int k = i >> 6, j = i & 63;
        w5_s[i] = (j < 32) ? Wm5[k * 32 + j] : Ws5[k * 32 + (j - 32)];
    }
    for (int idx = tid; idx < NPB * H; idx += 256) {
        const int node = idx / H, h = idx % H;
        const int g = gBase + node;
        const int nch = g & (NCHAIN - 1);
        float el, er;
        if (nch == 0)               { el = 0.f; er = 1.f; }
        else if (nch == NCHAIN - 1) { el = 1.f; er = 0.f; }
        else {
            const float al = g_alpha[(size_t)(g - 1) * H + h];
            const float ar = g_alpha[(size_t)(g + 1) * H + h];
            const float mx = fmaxf(al, ar);
            el = expf(al - mx); er = expf(ar - mx);
        }
        const float inv = (1.f / ((el + er) + 1e-16f)) * (1.f / H);
        wl_s[idx] = el * inv;
        wr_s[idx] = er * inv;
    }
    __syncthreads();

    // ---- phase A: agg (layer-4 output with ELU) into x_s ----
    {
        const int lane = tid % TPN, node = tid / TPN;
        const int g = gBase + node;
        const int nch = g & (NCHAIN - 1);
        const __half* rowL = ymsg + (size_t)((nch > 0)          ? g - 1 : g) * 1024;
        const __half* rowR = ymsg + (size_t)((nch < NCHAIN - 1) ? g + 1 : g) * 1024;
        const int c8 = lane * 8;

        float acc[8];
        #pragma unroll
        for (int e = 0; e < 8; e++) acc[e] = 0.f;
        #pragma unroll
        for (int h = 0; h < H; h++) {
            const float wl = wl_s[node * H + h];
            const float wr = wr_s[node * H + h];
            const uint4 uL = *reinterpret_cast<const uint4*>(rowL + h * C + c8);
            const uint4 uR = *reinterpret_cast<const uint4*>(rowR + h * C + c8);
            const uint32_t* pL = &uL.x;
            const uint32_t* pR = &uR.x;
            #pragma unroll
            for (int q = 0; q < 4; q++) {
                const float2 l = __half22float2(*reinterpret_cast<const __half2*>(&pL[q]));
                const float2 r = __half22float2(*reinterpret_cast<const __half2*>(&pR[q]));
                acc[2 * q]     = fmaf(wl, l.x, fmaf(wr, r.x, acc[2 * q]));
                acc[2 * q + 1] = fmaf(wl, l.y, fmaf(wr, r.y, acc[2 * q + 1]));
            }
        }
        const float4 s0 = *reinterpret_cast<const float4*>(yself + (size_t)g * 128 + c8);
        const float4 s1 = *reinterpret_cast<const float4*>(yself + (size_t)g * 128 + c8 + 4);
        acc[0] += s0.x; acc[1] += s0.y; acc[2] += s0.z; acc[3] += s0.w;
        acc[4] += s1.x; acc[5] += s1.y; acc[6] += s1.z; acc[7] += s1.w;
        #pragma unroll
        for (int e = 0; e < 8; e++) {
            const float v = (acc[e] > 0.f) ? acc[e] : expm1f(acc[e]);  // ELU
            x_s[node * 64 + c8 + e] = v;
        }
    }
    __syncthreads();

    // ---- phase B: layer-5 msg (cols 0..31, leaky) + self (cols 32..63) ----
    {
        const int node = tid >> 3;
        const int sub  = tid & 7;
        const int j8   = sub * 8;
        const int g = gBase + node;
        const float* xr = x_s + node * 64;

        float v[8];
        #pragma unroll
        for (int j = 0; j < 8; j++) {
            const int col = j8 + j;
            v[j] = (col < 32) ? __ldg(&bm5[col]) : __ldg(&bs5[col - 32]);
        }
        #pragma unroll 4
        for (int k = 0; k < 64; k++) {
            const float xv = xr[k];
            const float* wrow = w5_s + k * 64 + j8;
            #pragma unroll
            for (int j = 0; j < 8; j++)
                v[j] = fmaf(xv, wrow[j], v[j]);
        }

        float p = 0.f;
        if (sub < 4) {
            #pragma unroll
            for (int j = 0; j < 8; j++) {
                v[j] = leaky(v[j]);
                p = fmaf(v[j], __ldg(&att5[j8 + j]), p);
            }
        }
        // reduce alpha over the 4 msg threads of this node (width-8 group)
        p += __shfl_down_sync(0xffffffffu, p, 4, 8);
        p += __shfl_down_sync(0xffffffffu, p, 2, 8);
        p += __shfl_down_sync(0xffffffffu, p, 1, 8);
        if (sub == 0) g_alpha5[g] = p;

        float4* dst = reinterpret_cast<float4*>(y5 + (size_t)g * 64 + j8);
        dst[0] = make_float4(v[0], v[1], v[2], v[3]);
        dst[1] = make_float4(v[4], v[5], v[6], v[7]);
    }
}

// fp32 agg for layer 5 (C=32, H=1, stride 64)
__global__ __launch_bounds__(256) void agg5(
    const float* __restrict__ y, float* __restrict__ xout)
{
    constexpr int TPN = 8, NPB = 32;
    __shared__ float wl_s[NPB], wr_s[NPB];
    const int tid = threadIdx.x;
    const int gBase = blockIdx.x * NPB;

    if (tid < NPB) {
        const int g = gBase + tid;
        const int nch = g & (NCHAIN - 1);
        float el, er;
        if (nch == 0)               { el = 0.f; er = 1.f; }
        else if (nch == NCHAIN - 1) { el = 1.f; er = 0.f; }
        else {
            const float al = g_alpha5[(size_t)(g - 1)];
            const float ar = g_alpha5[(size_t)(g + 1)];
            const float mx = fmaxf(al, ar);
            el = expf(al - mx); er = expf(ar - mx);
        }
        const float inv = 1.f / ((el + er) + 1e-16f);
        wl_s[tid] = el * inv;
        wr_s[tid] = er * inv;
    }
    __syncthreads();

    const int lane = tid % TPN, node = tid / TPN;
    const int g = gBase + node;
    const int nch = g & (NCHAIN - 1);
    const float* rowL = y + (size_t)((nch > 0)          ? g - 1 : g) * 64;
    const float* rowR = y + (size_t)((nch < NCHAIN - 1) ? g + 1 : g) * 64;
    const int c4 = lane * 4;
    const float wl = wl_s[node], wr = wr_s[node];
    const float4 mL = *reinterpret_cast<const float4*>(rowL + c4);
    const float4 mR = *reinterpret_cast<const float4*>(rowR + c4);
    const float4 sv = *reinterpret_cast<const float4*>(y + (size_t)g * 64 + 32 + c4);
    float4 acc;
    acc.x = fmaf(wl, mL.x, fmaf(wr, mR.x, sv.x));
    acc.y = fmaf(wl, mL.y, fmaf(wr, mR.y, sv.y));
    acc.z = fmaf(wl, mL.z, fmaf(wr, mR.z, sv.z));
    acc.w = fmaf(wl, mL.w, fmaf(wr, mR.w, sv.w));
    *reinterpret_cast<float4*>(xout + (size_t)g * 32 + c4) = acc;
}

// ================= readout =================
__global__ __launch_bounds__(1024) void final_k(
    const float* __restrict__ x5, const float* __restrict__ Wc,
    const float* __restrict__ bc, float* __restrict__ out, int out_size)
{
    const int tid = threadIdx.x;
    const int b = tid >> 5;
    const int c = tid & 31;
    const float v = x5[((size_t)b * NCHAIN + (NCHAIN - 1)) * 32 + c];
    if (32 + tid < out_size) out[32 + tid] = v;
    float p = v * __ldg(&Wc[c]);
    #pragma unroll
    for (int off = 16; off > 0; off >>= 1)
        p += __shfl_down_sync(0xffffffffu, p, off);
    if (c == 0 && b < out_size) out[b] = p + __ldg(&bc[0]);
}

// ================= launch =================
extern "C" void kernel_launch(void* const* d_in, const int* in_sizes, int n_in,
                              void* d_out, int out_size)
{
    const float* nodes = (const float*)d_in[0];
    const float* Wm1 = (const float*)d_in[1];  const float* bm1 = (const float*)d_in[2];
    const float* Ws1 = (const float*)d_in[3];  const float* bs1 = (const float*)d_in[4];
    const float* att1 = (const float*)d_in[5];
    const float* Wm2 = (const float*)d_in[6];  const float* bm2 = (const float*)d_in[7];
    const float* Ws2 = (const float*)d_in[8];  const float* bs2 = (const float*)d_in[9];
    const float* att2 = (const float*)d_in[10];
    const float* Wm3 = (const float*)d_in[11]; const float* bm3 = (const float*)d_in[12];
    const float* Ws3 = (const float*)d_in[13]; const float* bs3 = (const float*)d_in[14];
    const float* att3 = (const float*)d_in[15];
    const float* Wm4 = (const float*)d_in[16]; const float* bm4 = (const float*)d_in[17];
    const float* Ws4 = (const float*)d_in[18]; const float* bs4 = (const float*)d_in[19];
    const float* att4 = (const float*)d_in[20];
    const float* Wm5 = (const float*)d_in[21]; const float* bm5 = (const float*)d_in[22];
    const float* Ws5 = (const float*)d_in[23]; const float* bs5 = (const float*)d_in[24];
    const float* att5 = (const float*)d_in[25];
    const float* Wc  = (const float*)d_in[26]; const float* bc  = (const float*)d_in[27];

    __half *ymsg, *xq, *w16;
    float *yself, *bufA, *bufB, *bias;
    cudaGetSymbolAddress((void**)&ymsg,  g_ymsg);
    cudaGetSymbolAddress((void**)&yself, g_yself);
    cudaGetSymbolAddress((void**)&bufA,  g_bufA);
    cudaGetSymbolAddress((void**)&bufB,  g_bufB);
    cudaGetSymbolAddress((void**)&xq,    g_xq);
    cudaGetSymbolAddress((void**)&w16,   g_w16);
    cudaGetSymbolAddress((void**)&bias,  g_bias);

    // sA + sB + sStage + alpha
    const int SM128 = (64 * 136 + 128 * 136) * 2 + 64 * 136 * 2 + 1024;  // 70,656 B
    const int SM64  = (64 * 72  + 128 * 72)  * 2 + 64 * 136 * 2 + 1024;  // 46,080 B
    cudaFuncSetAttribute(gemm_mma<128, 128>, cudaFuncAttributeMaxDynamicSharedMemorySize, SM128);
    cudaFuncSetAttribute(gemm_mma<128, 64>,  cudaFuncAttributeMaxDynamicSharedMemorySize, SM128);
    cudaFuncSetAttribute(gemm_mma<64, 64>,   cudaFuncAttributeMaxDynamicSharedMemorySize, SM64);

    const int WTOT = 2 * 1152 * 128 + 1152 * 64;
    convert_w_all<<<(WTOT + 255) / 256, 256>>>(Wm2, bm2, Ws2, bs2,
                                               Wm3, bm3, Ws3, bs3,
                                               Wm4, bm4, Ws4, bs4, w16, bias);

    // Layer 1
    alpha1<<<NUMNODES / 32, 256>>>(nodes, Wm1, bm1, att1);
    out1<<<NUMNODES / 32, 256>>>(nodes, Wm1, bm1, Ws1, bs1, xq);

    const dim3 GG(NUMNODES / 64, 5);

    // Layer 2: K=128, C=128
    gemm_mma<128, 128><<<GG, 256, SM128>>>(xq, w16 + 0 * WSLOT,
                                           bias + 0 * 1152, att2, ymsg, yself);
    agg2h<128, 8><<<NUMNODES / 16, 256>>>(ymsg, yself, xq);

    // Layer 3: K=128, C=64
    gemm_mma<128, 64><<<GG, 256, SM128>>>(xq, w16 + 1 * WSLOT,
                                          bias + 1 * 1152, att3, ymsg, yself);
    agg2h<64, 16><<<NUMNODES / 32, 256>>>(ymsg, yself, xq);

    // Layer 4: K=64, C=64 -> fused agg + layer-5 msg/self
    gemm_mma<64, 64><<<GG, 256, SM64>>>(xq, w16 + 2 * WSLOT,
                                        bias + 2 * 1152, att4, ymsg, yself);
    agg4f<<<NUMNODES / 32, 256>>>(ymsg, yself, Wm5, bm5, Ws5, bs5, att5, bufB);

    // Layer 5 softmax-agg
    agg5<<<NUMNODES / 32, 256>>>(bufB, bufA);

    final_k<<<1, 1024>>>(bufA, Wc, bc, (float*)d_out, out_size);
}

// round 15
// speedup vs baseline: 5.8167x; 5.8167x over previous
#include <cuda_runtime.h>
#include <cstdint>
#include <cstddef>

// The reference output depends ONLY on the last node (index 1023) of each
// of the 32 chains. The 5-layer 2-neighbor stencil cone of that node spans
// input nodes 1018..1023. One block per graph computes the whole cone in
// shared memory, full fp32.
//
// Node sets (chain-local):
//   input x0 : 1018..1023 (6)
//   x1       : 1019..1023 (5)   msg1/alpha1 at 1018..1023 (6)
//   x2       : 1020..1023 (4)   msg2/alpha2 at 1019..1023 (5)
//   x3       : 1021..1023 (3)   msg3/alpha3 at 1020..1023 (4)
//   x4       : 1022..1023 (2)   msg4/alpha4 at 1021..1023 (3)
//   x5       : 1023      (1)   msg5 at 1022 (edge weight = 1, H=1)

__device__ __forceinline__ float leaky(float v) { return (v > 0.f) ? v : 0.01f * v; }
__device__ __forceinline__ float elu(float v)   { return (v > 0.f) ? v : expm1f(v); }

__global__ __launch_bounds__(1024) void cone(
    const float* __restrict__ x,
    const float* __restrict__ Wm1, const float* __restrict__ bm1,
    const float* __restrict__ Ws1, const float* __restrict__ bs1,
    const float* __restrict__ att1,
    const float* __restrict__ Wm2, const float* __restrict__ bm2,
    const float* __restrict__ Ws2, const float* __restrict__ bs2,
    const float* __restrict__ att2,
    const float* __restrict__ Wm3, const float* __restrict__ bm3,
    const float* __restrict__ Ws3, const float* __restrict__ bs3,
    const float* __restrict__ att3,
    const float* __restrict__ Wm4, const float* __restrict__ bm4,
    const float* __restrict__ Ws4, const float* __restrict__ bs4,
    const float* __restrict__ att4,
    const float* __restrict__ Wm5, const float* __restrict__ bm5,
    const float* __restrict__ Ws5, const float* __restrict__ bs5,
    const float* __restrict__ att5,
    const float* __restrict__ Wc,  const float* __restrict__ bc,
    float* __restrict__ out, int out_size)
{
    __shared__ float msg[6][1024];     // per-node messages of current layer
    __shared__ float wpart[6][32];     // per-warp alpha partials
    __shared__ float alpha[6][16];     // attention logits per (node, head)
    __shared__ float wgt[5][32];       // softmax weights: wl[0..15] | wr[16..31]
    __shared__ float xA[6][128];       // activation ping
    __shared__ float xB[5][128];       // activation pong
    __shared__ float selfb[4][128];    // self-linear results

    const int tid  = threadIdx.x;
    const int lane = tid & 31;
    const int wrp  = tid >> 5;
    const size_t gb = (size_t)blockIdx.x * 1024;

    // ---- input: x0 at nodes 1018..1023 ----
    if (tid < 6) xA[tid][0] = x[gb + 1018 + tid];
    __syncthreads();

    // ======== Layer 1 (cin=1, H=8, C=128) ========
    {
        const float wm = __ldg(&Wm1[tid]);
        const float bm = __ldg(&bm1[tid]);
        const float at = __ldg(&att1[tid]);
        #pragma unroll
        for (int i = 0; i < 6; i++) {
            const float m = leaky(fmaf(xA[i][0], wm, bm));
            msg[i][tid] = m;
            float p = m * at;
            #pragma unroll
            for (int o = 16; o > 0; o >>= 1) p += __shfl_xor_sync(~0u, p, o);
            if (lane == 0) wpart[i][wrp] = p;
        }
    }
    __syncthreads();
    if (tid < 48) {                        // alpha1: 6 nodes x 8 heads
        const int i = tid >> 3, h = tid & 7;
        alpha[i][h] = wpart[i][4*h] + wpart[i][4*h+1] + wpart[i][4*h+2] + wpart[i][4*h+3];
    }
    __syncthreads();
    if (tid < 40) {                        // softmax weights for x1 (nodes 1019+v)
        const int v = tid >> 3, h = tid & 7, i = v + 1;
        const bool hasR = (i < 5);
        const float al = alpha[i-1][h];
        const float ar = hasR ? alpha[i+1][h] : -1e30f;
        const float mx = fmaxf(al, ar);
        const float el = expf(al - mx);
        const float er = hasR ? expf(ar - mx) : 0.f;
        const float inv = (1.f / ((el + er) + 1e-16f)) * 0.125f;   // /H=8
        wgt[v][h] = el * inv; wgt[v][16+h] = er * inv;
    }
    __syncthreads();
    if (tid < 640) {                       // x1 at v=0..4 (nodes 1019..1023)
        const int v = tid >> 7, c = tid & 127, i = v + 1;
        const int ir = (i < 5) ? i + 1 : i;    // wr==0 when clamped
        float a = 0.f;
        #pragma unroll
        for (int h = 0; h < 8; h++) {
            a = fmaf(wgt[v][h],    msg[i-1][h*128 + c], a);
            a = fmaf(wgt[v][16+h], msg[ir][h*128 + c],  a);
        }
        a += fmaf(xA[i][0], __ldg(&Ws1[c]), __ldg(&bs1[c]));
        xB[v][c] = elu(a);
    }
    __syncthreads();

    // ======== Layer 2 (cin=128, H=8, C=128); x1 in xB[0..4] ========
    {
        float acc[5];
        const float bm = __ldg(&bm2[tid]);
        #pragma unroll
        for (int n = 0; n < 5; n++) acc[n] = bm;
        #pragma unroll 8
        for (int k = 0; k < 128; k++) {
            const float w = __ldg(&Wm2[k*1024 + tid]);
            #pragma unroll
            for (int n = 0; n < 5; n++) acc[n] = fmaf(xB[n][k], w, acc[n]);
        }
        const float at = __ldg(&att2[tid]);
        #pragma unroll
        for (int n = 0; n < 5; n++) {
            const float m = leaky(acc[n]);
            msg[n][tid] = m;
            float p = m * at;
            #pragma unroll
            for (int o = 16; o > 0; o >>= 1) p += __shfl_xor_sync(~0u, p, o);
            if (lane == 0) wpart[n][wrp] = p;
        }
    }
    __syncthreads();
    if (tid < 40) {                        // alpha2: 5 nodes x 8 heads
        const int n = tid >> 3, h = tid & 7;
        alpha[n][h] = wpart[n][4*h] + wpart[n][4*h+1] + wpart[n][4*h+2] + wpart[n][4*h+3];
    }
    if (tid < 512) {                       // self2 at nodes 1020..1023 (xB idx v+1)
        const int v = tid >> 7, c = tid & 127;
        float s = __ldg(&bs2[c]);
        #pragma unroll 8
        for (int k = 0; k < 128; k++)
            s = fmaf(xB[v+1][k], __ldg(&Ws2[k*128 + c]), s);
        selfb[v][c] = s;
    }
    __syncthreads();
    if (tid < 32) {                        // weights for x2 (nodes 1020+v)
        const int v = tid >> 3, h = tid & 7, i = v + 1;
        const bool hasR = (i < 4);
        const float al = alpha[i-1][h];
        const float ar = hasR ? alpha[i+1][h] : -1e30f;
        const float mx = fmaxf(al, ar);
        const float el = expf(al - mx);
        const float er = hasR ? expf(ar - mx) : 0.f;
        const float inv = (1.f / ((el + er) + 1e-16f)) * 0.125f;
        wgt[v][h] = el * inv; wgt[v][16+h] = er * inv;
    }
    __syncthreads();
    if (tid < 512) {                       // x2 at v=0..3 (nodes 1020..1023)
        const int v = tid >> 7, c = tid & 127, i = v + 1;
        const int ir = (i < 4) ? i + 1 : i;
        float a = 0.f;
        #pragma unroll
        for (int h = 0; h < 8; h++) {
            a = fmaf(wgt[v][h],    msg[i-1][h*128 + c], a);
            a = fmaf(wgt[v][16+h], msg[ir][h*128 + c],  a);
        }
        a += selfb[v][c];
        xA[v][c] = elu(a);
    }
    __syncthreads();

    // ======== Layer 3 (cin=128, H=16, C=64); x2 in xA[0..3] ========
    {
        float acc[4];
        const float bm = __ldg(&bm3[tid]);
        #pragma unroll
        for (int n = 0; n < 4; n++) acc[n] = bm;
        #pragma unroll 8
        for (int k = 0; k < 128; k++) {
            const float w = __ldg(&Wm3[k*1024 + tid]);
            #pragma unroll
            for (int n = 0; n < 4; n++) acc[n] = fmaf(xA[n][k], w, acc[n]);
        }
        const float at = __ldg(&att3[tid]);
        #pragma unroll
        for (int n = 0; n < 4; n++) {
            const float m = leaky(acc[n]);
            msg[n][tid] = m;
            float p = m * at;
            #pragma unroll
            for (int o = 16; o > 0; o >>= 1) p += __shfl_xor_sync(~0u, p, o);
            if (lane == 0) wpart[n][wrp] = p;
        }
    }
    __syncthreads();
    if (tid < 64) {                        // alpha3: 4 nodes x 16 heads (C=64)
        const int n = tid >> 4, h = tid & 15;
        alpha[n][h] = wpart[n][2*h] + wpart[n][2*h+1];
    }
    if (tid < 192) {                       // self3 at nodes 1021..1023 (xA idx v+1)
        const int v = tid >> 6, c = tid & 63;
        float s = __ldg(&bs3[c]);
        #pragma unroll 8
        for (int k = 0; k < 128; k++)
            s = fmaf(xA[v+1][k], __ldg(&Ws3[k*64 + c]), s);
        selfb[v][c] = s;
    }
    __syncthreads();
    if (tid < 48) {                        // weights for x3 (nodes 1021+v)
        const int v = tid >> 4, h = tid & 15, i = v + 1;
        const bool hasR = (i < 3);
        const float al = alpha[i-1][h];
        const float ar = hasR ? alpha[i+1][h] : -1e30f;
        const float mx = fmaxf(al, ar);
        const float el = expf(al - mx);
        const float er = hasR ? expf(ar - mx) : 0.f;
        const float inv = (1.f / ((el + er) + 1e-16f)) * 0.0625f;  // /H=16
        wgt[v][h] = el * inv; wgt[v][16+h] = er * inv;
    }
    __syncthreads();
    if (tid < 192) {                       // x3 at v=0..2 (nodes 1021..1023), 64-wide
        const int v = tid >> 6, c = tid & 63, i = v + 1;
        const int ir = (i < 3) ? i + 1 : i;
        float a = 0.f;
        #pragma unroll
        for (int h = 0; h < 16; h++) {
            a = fmaf(wgt[v][h],    msg[i-1][h*64 + c], a);
            a = fmaf(wgt[v][16+h], msg[ir][h*64 + c],  a);
        }
        a += selfb[v][c];
        xB[v][c] = elu(a);
    }
    __syncthreads();

    // ======== Layer 4 (cin=64, H=16, C=64); x3 in xB[0..2] ========
    {
        float acc[3];
        const float bm = __ldg(&bm4[tid]);
        #pragma unroll
        for (int n = 0; n < 3; n++) acc[n] = bm;
        #pragma unroll 8
        for (int k = 0; k < 64; k++) {
            const float w = __ldg(&Wm4[k*1024 + tid]);
            #pragma unroll
            for (int n = 0; n < 3; n++) acc[n] = fmaf(xB[n][k], w, acc[n]);
        }
        const float at = __ldg(&att4[tid]);
        #pragma unroll
        for (int n = 0; n < 3; n++) {
            const float m = leaky(acc[n]);
            msg[n][tid] = m;
            float p = m * at;
            #pragma unroll
            for (int o = 16; o > 0; o >>= 1) p += __shfl_xor_sync(~0u, p, o);
            if (lane == 0) wpart[n][wrp] = p;
        }
    }
    __syncthreads();
    if (tid < 48) {                        // alpha4: 3 nodes x 16 heads
        const int n = tid >> 4, h = tid & 15;
        alpha[n][h] = wpart[n][2*h] + wpart[n][2*h+1];
    }
    if (tid < 128) {                       // self4 at nodes 1022,1023 (xB idx v+1)
        const int v = tid >> 6, c = tid & 63;
        float s = __ldg(&bs4[c]);
        #pragma unroll 8
        for (int k = 0; k < 64; k++)
            s = fmaf(xB[v+1][k], __ldg(&Ws4[k*64 + c]), s);
        selfb[v][c] = s;
    }
    __syncthreads();
    if (tid < 32) {                        // weights for x4 (nodes 1022+v)
        const int v = tid >> 4, h = tid & 15, i = v + 1;
        const bool hasR = (i < 2);
        const float al = alpha[i-1][h];
        const float ar = hasR ? alpha[i+1][h] : -1e30f;
        const float mx = fmaxf(al, ar);
        const float el = expf(al - mx);
        const float er = hasR ? expf(ar - mx) : 0.f;
        const float inv = (1.f / ((el + er) + 1e-16f)) * 0.0625f;
        wgt[v][h] = el * inv; wgt[v][16+h] = er * inv;
    }
    __syncthreads();
    if (tid < 128) {                       // x4 at v=0..1 (nodes 1022,1023)
        const int v = tid >> 6, c = tid & 63, i = v + 1;
        const int ir = (i < 2) ? i + 1 : i;
        float a = 0.f;
        #pragma unroll
        for (int h = 0; h < 16; h++) {
            a = fmaf(wgt[v][h],    msg[i-1][h*64 + c], a);
            a = fmaf(wgt[v][16+h], msg[ir][h*64 + c],  a);
        }
        a += selfb[v][c];
        xA[v][c] = elu(a);
    }
    __syncthreads();

    // ======== Layer 5 (cin=64, H=1, C=32) + readout ========
    // Node 1023: single incoming edge (from 1022) -> softmax weight 1, head mean = identity.
    if (tid < 32) {
        float m = __ldg(&bm5[tid]);
        float s = __ldg(&bs5[tid]);
        #pragma unroll 8
        for (int k = 0; k < 64; k++) {
            m = fmaf(xA[0][k], __ldg(&Wm5[k*32 + tid]), m);   // msg at 1022
            s = fmaf(xA[1][k], __ldg(&Ws5[k*32 + tid]), s);   // self at 1023
        }
        m = leaky(m);
        const float o5 = m + s;                               // no ELU on layer 5
        const int fidx = 32 + (int)blockIdx.x * 32 + tid;
        if (fidx < out_size) out[fidx] = o5;
        float p = o5 * __ldg(&Wc[tid]);
        #pragma unroll
        for (int o = 16; o > 0; o >>= 1) p += __shfl_xor_sync(~0u, p, o);
        if (tid == 0 && (int)blockIdx.x < out_size) out[blockIdx.x] = p + __ldg(&bc[0]);
    }
}

// ================= launch =================
extern "C" void kernel_launch(void* const* d_in, const int* in_sizes, int n_in,
                              void* d_out, int out_size)
{
    const float* nodes = (const float*)d_in[0];
    const float* Wm1 = (const float*)d_in[1];  const float* bm1 = (const float*)d_in[2];
    const float* Ws1 = (const float*)d_in[3];  const float* bs1 = (const float*)d_in[4];
    const float* att1 = (const float*)d_in[5];
    const float* Wm2 = (const float*)d_in[6];  const float* bm2 = (const float*)d_in[7];
    const float* Ws2 = (const float*)d_in[8];  const float* bs2 = (const float*)d_in[9];
    const float* att2 = (const float*)d_in[10];
    const float* Wm3 = (const float*)d_in[11]; const float* bm3 = (const float*)d_in[12];
    const float* Ws3 = (const float*)d_in[13]; const float* bs3 = (const float*)d_in[14];
    const float* att3 = (const float*)d_in[15];
    const float* Wm4 = (const float*)d_in[16]; const float* bm4 = (const float*)d_in[17];
    const float* Ws4 = (const float*)d_in[18]; const float* bs4 = (const float*)d_in[19];
    const float* att4 = (const float*)d_in[20];
    const float* Wm5 = (const float*)d_in[21]; const float* bm5 = (const float*)d_in[22];
    const float* Ws5 = (const float*)d_in[23]; const float* bs5 = (const float*)d_in[24];
    const float* att5 = (const float*)d_in[25];
    const float* Wc  = (const float*)d_in[26]; const float* bc  = (const float*)d_in[27];

    cone<<<32, 1024>>>(nodes,
                       Wm1, bm1, Ws1, bs1, att1,
                       Wm2, bm2, Ws2, bs2, att2,
                       Wm3, bm3, Ws3, bs3, att3,
                       Wm4, bm4, Ws4, bs4, att4,
                       Wm5, bm5, Ws5, bs5, att5,
                       Wc, bc, (float*)d_out, out_size);
}